// round 15
// baseline (speedup 1.0000x reference)
#include <cuda_runtime.h>
#include <cuda_bf16.h>
#include <math.h>

typedef unsigned long long u64;
typedef unsigned int u32;

#define B_TOT 3072
#define NTOK  64
#define DIM   128
#define NH    4
#define NWIN  192
#define NTHR  512
#define QSCALE 0.1767766952966369f   // 32^-0.5
#define OUTS   0.8f                  // 1 - lambda_init

// fp32 tile swizzle: f4-unit index in [64 rows][32 f4]
__device__ __forceinline__ int SWZ(int row, int g) { return row * 32 + (g ^ (row & 31)); }
// bf16 image swizzle: byte offset in [64 rows][256B rows]
__device__ __forceinline__ int BSW(int r, int byte) {
    return r * 256 + ((((byte >> 4) ^ r) & 15) << 4) + (byte & 15);
}
// bf16 image swizzle for 128B rows (P image)
__device__ __forceinline__ int BSW128(int r, int byte) {
    return r * 128 + ((((byte >> 4) ^ r) & 7) << 4) + (byte & 15);
}

// ---------------- mma.sync helpers (portable sm_80+ ISA) ----------------
__device__ __forceinline__ u32 sptr(const void* p) { return (u32)__cvta_generic_to_shared(p); }
__device__ __forceinline__ void ldsm4(u32 r[4], u32 addr) {
    asm volatile("ldmatrix.sync.aligned.m8n8.x4.shared.b16 {%0,%1,%2,%3}, [%4];"
                 : "=r"(r[0]), "=r"(r[1]), "=r"(r[2]), "=r"(r[3]) : "r"(addr));
}
__device__ __forceinline__ void ldsm2(u32 r[2], u32 addr) {
    asm volatile("ldmatrix.sync.aligned.m8n8.x2.shared.b16 {%0,%1}, [%2];"
                 : "=r"(r[0]), "=r"(r[1]) : "r"(addr));
}
__device__ __forceinline__ void ldsm2t(u32 r[2], u32 addr) {
    asm volatile("ldmatrix.sync.aligned.m8n8.x2.trans.shared.b16 {%0,%1}, [%2];"
                 : "=r"(r[0]), "=r"(r[1]) : "r"(addr));
}
__device__ __forceinline__ void mma16816(float d[4], const u32 a[4], const u32 b[2]) {
    asm volatile("mma.sync.aligned.m16n8k16.row.col.f32.bf16.bf16.f32 "
                 "{%0,%1,%2,%3}, {%4,%5,%6,%7}, {%8,%9}, {%0,%1,%2,%3};"
                 : "+f"(d[0]), "+f"(d[1]), "+f"(d[2]), "+f"(d[3])
                 : "r"(a[0]), "r"(a[1]), "r"(a[2]), "r"(a[3]), "r"(b[0]), "r"(b[1]));
}
__device__ __forceinline__ unsigned short bfbits(__nv_bfloat16 h) {
    return *reinterpret_cast<unsigned short*>(&h);
}

__device__ float g_pb[NH * NTOK * NTOK];
__device__ float g_pbm[NWIN * NH * NTOK * NTOK];
__device__ float g_lam;
// weights in mma B-fragment order:
// [chunk 0..11][img hi/lo][kt 0..7][nt 0..7][lane 0..31] -> u64 {b0,b1}
__device__ u64 g_wf[12 * 2 * 8 * 8 * 32];

// ---------------------------------------------------------------------------
__global__ void prep1_kernel(const float* __restrict__ Wp1, const float* __restrict__ bp1,
                             const float* __restrict__ Wp2, const float* __restrict__ bp2,
                             const float* __restrict__ lq1, const float* __restrict__ lk1,
                             const float* __restrict__ lq2, const float* __restrict__ lk2)
{
    int idx = blockIdx.x * blockDim.x + threadIdx.x;
    if (idx < NTOK * NTOK) {
        int i = idx >> 6, j = idx & 63;
        float dx = (float)(i & 7) - (float)(j & 7);
        float dy = -((float)(i >> 3) - (float)(j >> 3));
        float r  = sqrtf(dx * dx + dy * dy + 1e-9f);
        float th = atan2f(dx, dy);
        float p0 = r * 0.10101525445522107f;
        float p1 = (th + 3.14159265358979323846f) * 0.15915494309189535f;
        float o0 = __ldg(bp2 + 0), o1 = __ldg(bp2 + 1), o2 = __ldg(bp2 + 2), o3 = __ldg(bp2 + 3);
        for (int jj = 0; jj < 64; jj++) {
            float hv = fmaf(p0, __ldg(Wp1 + jj * 2), fmaf(p1, __ldg(Wp1 + jj * 2 + 1), __ldg(bp1 + jj)));
            float g  = 0.5f * hv * (1.0f + erff(hv * 0.7071067811865476f));
            o0 = fmaf(g, __ldg(Wp2 +       jj), o0);
            o1 = fmaf(g, __ldg(Wp2 +  64 + jj), o1);
            o2 = fmaf(g, __ldg(Wp2 + 128 + jj), o2);
            o3 = fmaf(g, __ldg(Wp2 + 192 + jj), o3);
        }
        g_pb[          idx] = o0;
        g_pb[ 4096 +   idx] = o1;
        g_pb[ 8192 +   idx] = o2;
        g_pb[12288 +   idx] = o3;
    }
    if (idx == 0) {
        float s1 = 0.f, s2 = 0.f;
        for (int k = 0; k < 16; k++) {
            s1 = fmaf(__ldg(lq1 + k), __ldg(lk1 + k), s1);
            s2 = fmaf(__ldg(lq2 + k), __ldg(lk2 + k), s2);
        }
        g_lam = expf(s1) - expf(s2) + 0.2f;
    }
}

__global__ void prep2_kernel(const float* __restrict__ mask)
{
    int idx = blockIdx.x * 256 + threadIdx.x;
    int rest = idx & 16383;
    int w    = idx >> 14;
    int nm   = idx & 4095;
    g_pbm[idx] = g_pb[rest] + __ldg(mask + w * 4096 + nm);
}

// Prep 3: weights -> hi/lo bf16, directly in mma B-fragment order.
__global__ void prepw_kernel(const float* __restrict__ Wqkv,
                             const float* __restrict__ Wqkv2,
                             const float* __restrict__ Wproj,
                             const float* __restrict__ subln)
{
    int idx = blockIdx.x * 256 + threadIdx.x;   // 0..49151 (one u64 each)
    int lane  = idx & 31;
    int nt    = (idx >> 5) & 7;
    int kt    = (idx >> 8) & 7;
    int img   = (idx >> 11) & 1;
    int chunk = idx >> 12;
    int cg = chunk * 64 + nt * 8 + (lane >> 2);
    int k0 = kt * 16 + (lane & 3) * 2;

    float v[4];
    int kk[4] = {k0, k0 + 1, k0 + 8, k0 + 9};
    #pragma unroll
    for (int j = 0; j < 4; j++) {
        int k = kk[j];
        float s, w;
        if (cg < 384)      { w = __ldg(Wqkv  + cg * 128 + k);         s = (cg < 128) ? QSCALE : 1.0f; }
        else if (cg < 640) { w = __ldg(Wqkv2 + (cg - 384) * 128 + k); s = (cg < 512) ? QSCALE : 1.0f; }
        else               { w = __ldg(Wproj + (cg - 640) * 128 + k); s = __ldg(subln + (k & 31)) * OUTS; }
        v[j] = w * s;
    }
    unsigned short b[4];
    #pragma unroll
    for (int j = 0; j < 4; j++) {
        __nv_bfloat16 h = __float2bfloat16(v[j]);
        if (img == 0) b[j] = bfbits(h);
        else          b[j] = bfbits(__float2bfloat16(v[j] - __bfloat162float(h)));
    }
    g_wf[idx] = (u64)b[0] | ((u64)b[1] << 16) | ((u64)b[2] << 32) | ((u64)b[3] << 48);
}

// ---------------------------------------------------------------------------
// Main fused kernel, 512 threads. smem bytes (total 229376):
//   [0,32768):       x bf16 hi/lo images (QKV) -> att fp32 (stride 68) -> os fp32 tile
//   [32768,65536):   P images hi@32768 lo@40960
//   [65536,98304):   q images hi/lo
//   [98304,131072):  k images hi/lo            -> os bf16 hi/lo images (proj)
//   [131072,163840): q2 images hi/lo
//   [163840,196608): k2 images hi/lo
//   [196608,229376): v images hi/lo
// ---------------------------------------------------------------------------
__global__ __launch_bounds__(NTHR) void wattn_kernel(
    const float* __restrict__ x,
    const float* __restrict__ bqkv, const float* __restrict__ bqkv2,
    const float* __restrict__ bproj,
    float* __restrict__ out)
{
    extern __shared__ float sm[];
    char* smc = (char*)sm;

    const int b = blockIdx.x;
    const int t = threadIdx.x;
    const int w = t >> 5, lid = t & 31;
    const int mg = w & 3, wg = w >> 2;
    const u32 smb = sptr(sm);

    // ---- load x, split to bf16 hi/lo swizzled images ----
    const float4* xg = (const float4*)(x + (size_t)b * (NTOK * DIM));
    #pragma unroll
    for (int i = 0; i < 4; i++) {
        int idx = t + i * NTHR;
        int token = idx >> 5, kb = idx & 31;
        float4 v = __ldg(xg + idx);
        __nv_bfloat16 h0 = __float2bfloat16(v.x), h1 = __float2bfloat16(v.y);
        __nv_bfloat16 h2 = __float2bfloat16(v.z), h3 = __float2bfloat16(v.w);
        __nv_bfloat16 l0 = __float2bfloat16(v.x - __bfloat162float(h0));
        __nv_bfloat16 l1 = __float2bfloat16(v.y - __bfloat162float(h1));
        __nv_bfloat16 l2 = __float2bfloat16(v.z - __bfloat162float(h2));
        __nv_bfloat16 l3 = __float2bfloat16(v.w - __bfloat162float(h3));
        u64 hp = (u64)bfbits(h0) | ((u64)bfbits(h1) << 16) | ((u64)bfbits(h2) << 32) | ((u64)bfbits(h3) << 48);
        u64 lp = (u64)bfbits(l0) | ((u64)bfbits(l1) << 16) | ((u64)bfbits(l2) << 32) | ((u64)bfbits(l3) << 48);
        int sw = BSW(token, kb * 8);
        *(u64*)(smc + sw)         = hp;
        *(u64*)(smc + 16384 + sw) = lp;
    }
    __syncthreads();

    // ---- QKV: A-fragments in regs (x images then dead); B-fragments from gmem ----
    {
        u32 xah[8][4], xal[8][4];
        {
            const int ar = mg * 16 + (lid & 15);
            const int ak = (lid & 16);
            #pragma unroll
            for (int kt = 0; kt < 8; kt++) {
                int off = BSW(ar, kt * 32 + ak);
                ldsm4(xah[kt], smb + off);
                ldsm4(xal[kt], smb + 16384 + off);
            }
        }
        #pragma unroll 1
        for (int ch = 0; ch < 10; ch++) {
            const u64* wf = g_wf + ch * 4096 + wg * 64 + lid;
            float d[2][4];
            #pragma unroll
            for (int nt = 0; nt < 2; nt++)
                #pragma unroll
                for (int i = 0; i < 4; i++) d[nt][i] = 0.f;
            #pragma unroll
            for (int kt = 0; kt < 8; kt++) {
                #pragma unroll
                for (int ntj = 0; ntj < 2; ntj++) {
                    u64 bhv = __ldg(wf + kt * 256 + ntj * 32);
                    u64 blv = __ldg(wf + 2048 + kt * 256 + ntj * 32);
                    u32 bh[2] = {(u32)bhv, (u32)(bhv >> 32)};
                    u32 bl[2] = {(u32)blv, (u32)(blv >> 32)};
                    mma16816(d[ntj], xah[kt], bh);
                    mma16816(d[ntj], xah[kt], bl);
                    mma16816(d[ntj], xal[kt], bh);
                }
            }
            const int ten = ch >> 1;
            const float bmult = (ten == 0 || ten == 3) ? QSCALE : 1.0f;
            const float* bsrc = (ten < 3) ? (bqkv + ten * 128) : (bqkv2 + (ten - 3) * 128);
            const int r0 = mg * 16 + (lid >> 2);
            const int ibase = (ten == 0) ? 65536 : (ten == 1) ? 98304
                            : (ten == 2) ? 196608 : (ten == 3) ? 131072 : 163840;
            char* img = smc + ibase;
            #pragma unroll
            for (int nt = 0; nt < 2; nt++) {
                int tc = (ch & 1) * 64 + wg * 16 + nt * 8 + 2 * (lid & 3);
                float b0 = __ldg(bsrc + tc) * bmult, b1 = __ldg(bsrc + tc + 1) * bmult;
                float v0 = d[nt][0] + b0, v1 = d[nt][1] + b1;
                float v2 = d[nt][2] + b0, v3 = d[nt][3] + b1;
                int c2 = tc * 2;
                __nv_bfloat16 h0 = __float2bfloat16(v0), h1 = __float2bfloat16(v1);
                __nv_bfloat16 h2 = __float2bfloat16(v2), h3 = __float2bfloat16(v3);
                u32 hp01 = (u32)bfbits(h0) | ((u32)bfbits(h1) << 16);
                u32 hp23 = (u32)bfbits(h2) | ((u32)bfbits(h3) << 16);
                __nv_bfloat16 l0 = __float2bfloat16(v0 - __bfloat162float(h0));
                __nv_bfloat16 l1 = __float2bfloat16(v1 - __bfloat162float(h1));
                __nv_bfloat16 l2 = __float2bfloat16(v2 - __bfloat162float(h2));
                __nv_bfloat16 l3 = __float2bfloat16(v3 - __bfloat162float(h3));
                u32 lp01 = (u32)bfbits(l0) | ((u32)bfbits(l1) << 16);
                u32 lp23 = (u32)bfbits(l2) | ((u32)bfbits(l3) << 16);
                int s0 = BSW(r0, c2), s1 = BSW(r0 + 8, c2);
                *(u32*)(img + s0)         = hp01;
                *(u32*)(img + 16384 + s0) = lp01;
                *(u32*)(img + s1)         = hp23;
                *(u32*)(img + 16384 + s1) = lp23;
            }
        }
    }
    __syncthreads();

    // ---- differential attention: R11 warp mapping, att in region A, 2 syncs/head ----
    const float lam = g_lam;
    const float* pbm = g_pbm + (size_t)(b % NWIN) * (NH * NTOK * NTOK);
    const int r0 = mg * 16 + (lid >> 2);
    const int n = t >> 3, qd = t & 7;
    float* att = sm;                          // region A, stride 68
    float o[4][4];
    #pragma unroll
    for (int h = 0; h < 4; h++)
        #pragma unroll
        for (int i = 0; i < 4; i++) o[h][i] = 0.f;

    #pragma unroll 1
    for (int h = 0; h < 4; h++) {
        // -- prefetch pbm (off the MMA->store critical path) --
        float2 pb0[2], pb1[2];
        #pragma unroll
        for (int nt = 0; nt < 2; nt++) {
            int col = wg * 16 + nt * 8 + 2 * (lid & 3);
            pb0[nt] = __ldg((const float2*)(pbm + h * 4096 + r0 * 64 + col));
            pb1[nt] = __ldg((const float2*)(pbm + h * 4096 + (r0 + 8) * 64 + col));
        }

        // -- logits: d1 = q.k^T, d2 = q2.k2^T (3-term hi/lo each) --
        {
            float d1[2][4], d2[2][4];
            #pragma unroll
            for (int nt = 0; nt < 2; nt++)
                #pragma unroll
                for (int i = 0; i < 4; i++) { d1[nt][i] = 0.f; d2[nt][i] = 0.f; }
            const int ar = mg * 16 + (lid & 15);
            const int abyte = h * 64 + (lid & 16);
            const int bc = wg * 16 + (lid & 7);
            const int bbyte = h * 64 + ((lid & 8) << 1);
            #pragma unroll
            for (int ks = 0; ks < 2; ks++) {
                u32 aoff = BSW(ar, abyte + ks * 32);
                u32 qh[4], ql[4], q2h[4], q2l[4];
                ldsm4(qh,  smb +  65536 + aoff);
                ldsm4(ql,  smb +  81920 + aoff);
                ldsm4(q2h, smb + 131072 + aoff);
                ldsm4(q2l, smb + 147456 + aoff);
                #pragma unroll
                for (int nt = 0; nt < 2; nt++) {
                    u32 boff = BSW(bc + nt * 8, bbyte + ks * 32);
                    u32 kh[2], kl[2], k2h[2], k2l[2];
                    ldsm2(kh,  smb +  98304 + boff);
                    ldsm2(kl,  smb + 114688 + boff);
                    ldsm2(k2h, smb + 163840 + boff);
                    ldsm2(k2l, smb + 180224 + boff);
                    mma16816(d1[nt], qh, kh);
                    mma16816(d1[nt], qh, kl);
                    mma16816(d1[nt], ql, kh);
                    mma16816(d2[nt], q2h, k2h);
                    mma16816(d2[nt], q2h, k2l);
                    mma16816(d2[nt], q2l, k2h);
                }
            }
            #pragma unroll
            for (int nt = 0; nt < 2; nt++) {
                int col = wg * 16 + nt * 8 + 2 * (lid & 3);
                *(float2*)(att + r0 * 68 + col) =
                    make_float2(fmaf(-lam, d2[nt][0], d1[nt][0]) + pb0[nt].x,
                                fmaf(-lam, d2[nt][1], d1[nt][1]) + pb0[nt].y);
                *(float2*)(att + (r0 + 8) * 68 + col) =
                    make_float2(fmaf(-lam, d2[nt][2], d1[nt][2]) + pb1[nt].x,
                                fmaf(-lam, d2[nt][3], d1[nt][3]) + pb1[nt].y);
            }
        }
        __syncthreads();   // att ready; also all prior-head AV P-reads complete

        // -- softmax: lane owns 8 contiguous cols [qd*8, qd*8+8) of row n;
        //    P images (region B) do not alias att (region A) --
        {
            float p[8];
            float4 L0 = *(const float4*)(att + n * 68 + qd * 8);
            float4 L1 = *(const float4*)(att + n * 68 + qd * 8 + 4);
            p[0] = L0.x; p[1] = L0.y; p[2] = L0.z; p[3] = L0.w;
            p[4] = L1.x; p[5] = L1.y; p[6] = L1.z; p[7] = L1.w;
            float M = p[0];
            #pragma unroll
            for (int j = 1; j < 8; j++) M = fmaxf(M, p[j]);
            M = fmaxf(M, __shfl_xor_sync(0xffffffffu, M, 1));
            M = fmaxf(M, __shfl_xor_sync(0xffffffffu, M, 2));
            M = fmaxf(M, __shfl_xor_sync(0xffffffffu, M, 4));
            float S = 0.f;
            #pragma unroll
            for (int j = 0; j < 8; j++) { p[j] = __expf(p[j] - M); S += p[j]; }
            S += __shfl_xor_sync(0xffffffffu, S, 1);
            S += __shfl_xor_sync(0xffffffffu, S, 2);
            S += __shfl_xor_sync(0xffffffffu, S, 4);
            float inv = 1.0f / S;
            u32 hp[4], lp[4];
            #pragma unroll
            for (int j = 0; j < 4; j++) {
                float v0 = p[2 * j] * inv, v1 = p[2 * j + 1] * inv;
                __nv_bfloat16 h0 = __float2bfloat16(v0), h1 = __float2bfloat16(v1);
                hp[j] = (u32)bfbits(h0) | ((u32)bfbits(h1) << 16);
                __nv_bfloat16 l0 = __float2bfloat16(v0 - __bfloat162float(h0));
                __nv_bfloat16 l1 = __float2bfloat16(v1 - __bfloat162float(h1));
                lp[j] = (u32)bfbits(l0) | ((u32)bfbits(l1) << 16);
            }
            int sw = BSW128(n, qd * 16);
            *(uint4*)(smc + 32768 + sw) = make_uint4(hp[0], hp[1], hp[2], hp[3]);
            *(uint4*)(smc + 40960 + sw) = make_uint4(lp[0], lp[1], lp[2], lp[3]);
        }
        __syncthreads();   // P ready

        // -- o[h] += P @ V via mma.sync (V fragment via ldmatrix.trans) --
        {
            const int ar = mg * 16 + (lid & 15);
            const int ak = (lid & 16);
            #pragma unroll
            for (int ks = 0; ks < 4; ks++) {
                u32 ph4[4], pl4[4];
                u32 paddr = smb + 32768 + BSW128(ar, ks * 32 + ak);
                ldsm4(ph4, paddr);
                ldsm4(pl4, paddr + 8192);
                u32 vh[2], vl[2];
                u32 vaddr = smb + 196608 + BSW(ks * 16 + (lid & 15), h * 64 + wg * 16);
                ldsm2t(vh, vaddr);
                ldsm2t(vl, vaddr + 16384);
                mma16816(o[h], ph4, vh);
                mma16816(o[h], ph4, vl);
                mma16816(o[h], pl4, vh);
            }
        }
        // next head: logit stores go to att (region A) — no conflict with P/V reads;
        // the sync after those stores protects P against overwrite (all AV done).
    }
    __syncthreads();   // att dead; all AV complete -> region A becomes os tile

    // ---- store o-fragments into os tile (region A) ----
    {
        float* ost = sm;
        #pragma unroll
        for (int h = 0; h < 4; h++) {
            int c = h * 32 + wg * 8 + 2 * (lid & 3);
            int g = c >> 2, sub = c & 3;
            *(float2*)(ost + SWZ(r0, g) * 4 + sub)     = make_float2(o[h][0], o[h][1]);
            *(float2*)(ost + SWZ(r0 + 8, g) * 4 + sub) = make_float2(o[h][2], o[h][3]);
        }
    }
    __syncthreads();

    // ---- RMSNorm fused with bf16 image conversion (os images -> k region) ----
    {
        const float* ost = (const float*)sm;
        #pragma unroll
        for (int h = 0; h < 4; h++) {
            int g = h * 8 + qd;
            float4 v4 = ((const float4*)ost)[SWZ(n, g)];
            float s = v4.x * v4.x + v4.y * v4.y + v4.z * v4.z + v4.w * v4.w;
            s += __shfl_xor_sync(0xffffffffu, s, 1);
            s += __shfl_xor_sync(0xffffffffu, s, 2);
            s += __shfl_xor_sync(0xffffffffu, s, 4);
            float rs = rsqrtf(s * (1.0f / 32.0f) + 1e-9f);
            v4.x *= rs; v4.y *= rs; v4.z *= rs; v4.w *= rs;
            __nv_bfloat16 h0 = __float2bfloat16(v4.x), h1 = __float2bfloat16(v4.y);
            __nv_bfloat16 h2 = __float2bfloat16(v4.z), h3 = __float2bfloat16(v4.w);
            __nv_bfloat16 l0 = __float2bfloat16(v4.x - __bfloat162float(h0));
            __nv_bfloat16 l1 = __float2bfloat16(v4.y - __bfloat162float(h1));
            __nv_bfloat16 l2 = __float2bfloat16(v4.z - __bfloat162float(h2));
            __nv_bfloat16 l3 = __float2bfloat16(v4.w - __bfloat162float(h3));
            u64 hp = (u64)bfbits(h0) | ((u64)bfbits(h1) << 16) | ((u64)bfbits(h2) << 32) | ((u64)bfbits(h3) << 48);
            u64 lp = (u64)bfbits(l0) | ((u64)bfbits(l1) << 16) | ((u64)bfbits(l2) << 32) | ((u64)bfbits(l3) << 48);
            int sw = BSW(n, g * 8);
            *(u64*)(smc +  98304 + sw) = hp;
            *(u64*)(smc + 114688 + sw) = lp;
        }
    }
    __syncthreads();

    // ---- proj: A-fragments from os images; B-fragments from gmem ----
    {
        u32 oah[8][4], oal[8][4];
        {
            const int ar = mg * 16 + (lid & 15);
            const int ak = (lid & 16);
            #pragma unroll
            for (int kt = 0; kt < 8; kt++) {
                int off = BSW(ar, kt * 32 + ak);
                ldsm4(oah[kt], smb +  98304 + off);
                ldsm4(oal[kt], smb + 114688 + off);
            }
        }
        float* og = out + (size_t)b * (NTOK * DIM);
        #pragma unroll 1
        for (int pc = 0; pc < 2; pc++) {
            const u64* wf = g_wf + (10 + pc) * 4096 + wg * 64 + lid;
            float d[2][4];
            #pragma unroll
            for (int nt = 0; nt < 2; nt++)
                #pragma unroll
                for (int i = 0; i < 4; i++) d[nt][i] = 0.f;
            #pragma unroll
            for (int kt = 0; kt < 8; kt++) {
                #pragma unroll
                for (int ntj = 0; ntj < 2; ntj++) {
                    u64 bhv = __ldg(wf + kt * 256 + ntj * 32);
                    u64 blv = __ldg(wf + 2048 + kt * 256 + ntj * 32);
                    u32 bh[2] = {(u32)bhv, (u32)(bhv >> 32)};
                    u32 bl[2] = {(u32)blv, (u32)(blv >> 32)};
                    mma16816(d[ntj], oah[kt], bh);
                    mma16816(d[ntj], oah[kt], bl);
                    mma16816(d[ntj], oal[kt], bh);
                }
            }
            #pragma unroll
            for (int nt = 0; nt < 2; nt++) {
                int cg = pc * 64 + wg * 16 + nt * 8 + 2 * (lid & 3);
                float b0 = __ldg(bproj + cg), b1 = __ldg(bproj + cg + 1);
                *(float2*)(og + r0 * 128 + cg)       = make_float2(d[nt][0] + b0, d[nt][1] + b1);
                *(float2*)(og + (r0 + 8) * 128 + cg) = make_float2(d[nt][2] + b0, d[nt][3] + b1);
            }
        }
    }
}

// ---------------------------------------------------------------------------
extern "C" void kernel_launch(void* const* d_in, const int* in_sizes, int n_in,
                              void* d_out, int out_size)
{
    const float* x      = (const float*)d_in[0];
    const float* mask   = (const float*)d_in[1];
    const float* Wqkv   = (const float*)d_in[2];
    const float* bqkv   = (const float*)d_in[3];
    const float* Wqkv2  = (const float*)d_in[4];
    const float* bqkv2  = (const float*)d_in[5];
    const float* Wp1    = (const float*)d_in[6];
    const float* bp1    = (const float*)d_in[7];
    const float* Wp2    = (const float*)d_in[8];
    const float* bp2    = (const float*)d_in[9];
    const float* lq1    = (const float*)d_in[10];
    const float* lk1    = (const float*)d_in[11];
    const float* lq2    = (const float*)d_in[12];
    const float* lk2    = (const float*)d_in[13];
    const float* subln  = (const float*)d_in[14];
    const float* Wproj  = (const float*)d_in[15];
    const float* bproj  = (const float*)d_in[16];
    float* out = (float*)d_out;

    const int SMEM = 229376;
    cudaFuncSetAttribute(wattn_kernel, cudaFuncAttributeMaxDynamicSharedMemorySize, SMEM);

    prep1_kernel<<<16, 256>>>(Wp1, bp1, Wp2, bp2, lq1, lk1, lq2, lk2);
    prep2_kernel<<<(NWIN * NH * NTOK * NTOK) / 256, 256>>>(mask);
    prepw_kernel<<<192, 256>>>(Wqkv, Wqkv2, Wproj, subln);
    wattn_kernel<<<B_TOT, NTHR, SMEM>>>(x, bqkv, bqkv2, bproj, out);
}

// round 16
// speedup vs baseline: 1.2512x; 1.2512x over previous
#include <cuda_runtime.h>
#include <cuda_bf16.h>
#include <math.h>

typedef unsigned long long u64;
typedef unsigned int u32;

#define B_TOT 3072
#define NTOK  64
#define DIM   128
#define NH    4
#define NWIN  192
#define NTHR  512
#define QSCALE 0.1767766952966369f   // 32^-0.5
#define OUTS   0.8f                  // 1 - lambda_init

// fp32 tile swizzle: f4-unit index in [64 rows][32 f4]
__device__ __forceinline__ int SWZ(int row, int g) { return row * 32 + (g ^ (row & 31)); }
// bf16 image swizzle: byte offset in [64 rows][256B rows]
__device__ __forceinline__ int BSW(int r, int byte) {
    return r * 256 + ((((byte >> 4) ^ r) & 15) << 4) + (byte & 15);
}
// bf16 image swizzle for 128B rows (P image)
__device__ __forceinline__ int BSW128(int r, int byte) {
    return r * 128 + ((((byte >> 4) ^ r) & 7) << 4) + (byte & 15);
}

// ---------------- mma.sync helpers (portable sm_80+ ISA) ----------------
__device__ __forceinline__ u32 sptr(const void* p) { return (u32)__cvta_generic_to_shared(p); }
__device__ __forceinline__ void ldsm4(u32 r[4], u32 addr) {
    asm volatile("ldmatrix.sync.aligned.m8n8.x4.shared.b16 {%0,%1,%2,%3}, [%4];"
                 : "=r"(r[0]), "=r"(r[1]), "=r"(r[2]), "=r"(r[3]) : "r"(addr));
}
__device__ __forceinline__ void ldsm2(u32 r[2], u32 addr) {
    asm volatile("ldmatrix.sync.aligned.m8n8.x2.shared.b16 {%0,%1}, [%2];"
                 : "=r"(r[0]), "=r"(r[1]) : "r"(addr));
}
__device__ __forceinline__ void ldsm2t(u32 r[2], u32 addr) {
    asm volatile("ldmatrix.sync.aligned.m8n8.x2.trans.shared.b16 {%0,%1}, [%2];"
                 : "=r"(r[0]), "=r"(r[1]) : "r"(addr));
}
__device__ __forceinline__ void mma16816(float d[4], const u32 a[4], const u32 b[2]) {
    asm volatile("mma.sync.aligned.m16n8k16.row.col.f32.bf16.bf16.f32 "
                 "{%0,%1,%2,%3}, {%4,%5,%6,%7}, {%8,%9}, {%0,%1,%2,%3};"
                 : "+f"(d[0]), "+f"(d[1]), "+f"(d[2]), "+f"(d[3])
                 : "r"(a[0]), "r"(a[1]), "r"(a[2]), "r"(a[3]), "r"(b[0]), "r"(b[1]));
}
__device__ __forceinline__ unsigned short bfbits(__nv_bfloat16 h) {
    return *reinterpret_cast<unsigned short*>(&h);
}

__device__ float g_pb[NH * NTOK * NTOK];
__device__ float g_pbm[NWIN * NH * NTOK * NTOK];
__device__ float g_lam;
// weights in mma B-fragment order:
// [chunk 0..11][img hi/lo][kt 0..7][nt 0..7][lane 0..31] -> u64 {b0,b1}
__device__ u64 g_wf[12 * 2 * 8 * 8 * 32];

// ---------------------------------------------------------------------------
__global__ void prep1_kernel(const float* __restrict__ Wp1, const float* __restrict__ bp1,
                             const float* __restrict__ Wp2, const float* __restrict__ bp2,
                             const float* __restrict__ lq1, const float* __restrict__ lk1,
                             const float* __restrict__ lq2, const float* __restrict__ lk2)
{
    int idx = blockIdx.x * blockDim.x + threadIdx.x;
    if (idx < NTOK * NTOK) {
        int i = idx >> 6, j = idx & 63;
        float dx = (float)(i & 7) - (float)(j & 7);
        float dy = -((float)(i >> 3) - (float)(j >> 3));
        float r  = sqrtf(dx * dx + dy * dy + 1e-9f);
        float th = atan2f(dx, dy);
        float p0 = r * 0.10101525445522107f;
        float p1 = (th + 3.14159265358979323846f) * 0.15915494309189535f;
        float o0 = __ldg(bp2 + 0), o1 = __ldg(bp2 + 1), o2 = __ldg(bp2 + 2), o3 = __ldg(bp2 + 3);
        for (int jj = 0; jj < 64; jj++) {
            float hv = fmaf(p0, __ldg(Wp1 + jj * 2), fmaf(p1, __ldg(Wp1 + jj * 2 + 1), __ldg(bp1 + jj)));
            float g  = 0.5f * hv * (1.0f + erff(hv * 0.7071067811865476f));
            o0 = fmaf(g, __ldg(Wp2 +       jj), o0);
            o1 = fmaf(g, __ldg(Wp2 +  64 + jj), o1);
            o2 = fmaf(g, __ldg(Wp2 + 128 + jj), o2);
            o3 = fmaf(g, __ldg(Wp2 + 192 + jj), o3);
        }
        g_pb[          idx] = o0;
        g_pb[ 4096 +   idx] = o1;
        g_pb[ 8192 +   idx] = o2;
        g_pb[12288 +   idx] = o3;
    }
    if (idx == 0) {
        float s1 = 0.f, s2 = 0.f;
        for (int k = 0; k < 16; k++) {
            s1 = fmaf(__ldg(lq1 + k), __ldg(lk1 + k), s1);
            s2 = fmaf(__ldg(lq2 + k), __ldg(lk2 + k), s2);
        }
        g_lam = expf(s1) - expf(s2) + 0.2f;
    }
}

__global__ void prep2_kernel(const float* __restrict__ mask)
{
    int idx = blockIdx.x * 256 + threadIdx.x;
    int rest = idx & 16383;
    int w    = idx >> 14;
    int nm   = idx & 4095;
    g_pbm[idx] = g_pb[rest] + __ldg(mask + w * 4096 + nm);
}

// Prep 3: weights -> hi/lo bf16, directly in mma B-fragment order.
__global__ void prepw_kernel(const float* __restrict__ Wqkv,
                             const float* __restrict__ Wqkv2,
                             const float* __restrict__ Wproj,
                             const float* __restrict__ subln)
{
    int idx = blockIdx.x * 256 + threadIdx.x;   // 0..49151 (one u64 each)
    int lane  = idx & 31;
    int nt    = (idx >> 5) & 7;
    int kt    = (idx >> 8) & 7;
    int img   = (idx >> 11) & 1;
    int chunk = idx >> 12;
    int cg = chunk * 64 + nt * 8 + (lane >> 2);
    int k0 = kt * 16 + (lane & 3) * 2;

    float v[4];
    int kk[4] = {k0, k0 + 1, k0 + 8, k0 + 9};
    #pragma unroll
    for (int j = 0; j < 4; j++) {
        int k = kk[j];
        float s, w;
        if (cg < 384)      { w = __ldg(Wqkv  + cg * 128 + k);         s = (cg < 128) ? QSCALE : 1.0f; }
        else if (cg < 640) { w = __ldg(Wqkv2 + (cg - 384) * 128 + k); s = (cg < 512) ? QSCALE : 1.0f; }
        else               { w = __ldg(Wproj + (cg - 640) * 128 + k); s = __ldg(subln + (k & 31)) * OUTS; }
        v[j] = w * s;
    }
    unsigned short b[4];
    #pragma unroll
    for (int j = 0; j < 4; j++) {
        __nv_bfloat16 h = __float2bfloat16(v[j]);
        if (img == 0) b[j] = bfbits(h);
        else          b[j] = bfbits(__float2bfloat16(v[j] - __bfloat162float(h)));
    }
    g_wf[idx] = (u64)b[0] | ((u64)b[1] << 16) | ((u64)b[2] << 32) | ((u64)b[3] << 48);
}

// ---------------------------------------------------------------------------
// Main fused kernel, 512 threads. smem bytes (total 229376):
//   [0,32768):       x bf16 hi/lo images (QKV) -> att fp32 (stride 68) -> os fp32 tile
//   [32768,65536):   P images hi@32768 lo@40960
//   [65536,98304):   q images hi/lo
//   [98304,131072):  k images hi/lo            -> os bf16 hi/lo images (proj)
//   [131072,163840): q2 images hi/lo
//   [163840,196608): k2 images hi/lo
//   [196608,229376): v images hi/lo
// ---------------------------------------------------------------------------
__global__ __launch_bounds__(NTHR) void wattn_kernel(
    const float* __restrict__ x,
    const float* __restrict__ bqkv, const float* __restrict__ bqkv2,
    const float* __restrict__ bproj,
    float* __restrict__ out)
{
    extern __shared__ float sm[];
    char* smc = (char*)sm;

    const int b = blockIdx.x;
    const int t = threadIdx.x;
    const int w = t >> 5, lid = t & 31;
    const int mg = w & 3, wg = w >> 2;
    const u32 smb = sptr(sm);

    // ---- load x, split to bf16 hi/lo swizzled images ----
    const float4* xg = (const float4*)(x + (size_t)b * (NTOK * DIM));
    #pragma unroll
    for (int i = 0; i < 4; i++) {
        int idx = t + i * NTHR;
        int token = idx >> 5, kb = idx & 31;
        float4 v = __ldg(xg + idx);
        __nv_bfloat16 h0 = __float2bfloat16(v.x), h1 = __float2bfloat16(v.y);
        __nv_bfloat16 h2 = __float2bfloat16(v.z), h3 = __float2bfloat16(v.w);
        __nv_bfloat16 l0 = __float2bfloat16(v.x - __bfloat162float(h0));
        __nv_bfloat16 l1 = __float2bfloat16(v.y - __bfloat162float(h1));
        __nv_bfloat16 l2 = __float2bfloat16(v.z - __bfloat162float(h2));
        __nv_bfloat16 l3 = __float2bfloat16(v.w - __bfloat162float(h3));
        u64 hp = (u64)bfbits(h0) | ((u64)bfbits(h1) << 16) | ((u64)bfbits(h2) << 32) | ((u64)bfbits(h3) << 48);
        u64 lp = (u64)bfbits(l0) | ((u64)bfbits(l1) << 16) | ((u64)bfbits(l2) << 32) | ((u64)bfbits(l3) << 48);
        int sw = BSW(token, kb * 8);
        *(u64*)(smc + sw)         = hp;
        *(u64*)(smc + 16384 + sw) = lp;
    }
    __syncthreads();

    // ---- QKV: A-fragments in regs (x images then dead); B-fragments from gmem ----
    {
        u32 xah[8][4], xal[8][4];
        {
            const int ar = mg * 16 + (lid & 15);
            const int ak = (lid & 16);
            #pragma unroll
            for (int kt = 0; kt < 8; kt++) {
                int off = BSW(ar, kt * 32 + ak);
                ldsm4(xah[kt], smb + off);
                ldsm4(xal[kt], smb + 16384 + off);
            }
        }
        #pragma unroll 1
        for (int ch = 0; ch < 10; ch++) {
            const u64* wf = g_wf + ch * 4096 + wg * 64 + lid;
            float d[2][4];
            #pragma unroll
            for (int nt = 0; nt < 2; nt++)
                #pragma unroll
                for (int i = 0; i < 4; i++) d[nt][i] = 0.f;
            #pragma unroll
            for (int kt = 0; kt < 8; kt++) {
                #pragma unroll
                for (int ntj = 0; ntj < 2; ntj++) {
                    u64 bhv = __ldg(wf + kt * 256 + ntj * 32);
                    u64 blv = __ldg(wf + 2048 + kt * 256 + ntj * 32);
                    u32 bh[2] = {(u32)bhv, (u32)(bhv >> 32)};
                    u32 bl[2] = {(u32)blv, (u32)(blv >> 32)};
                    mma16816(d[ntj], xah[kt], bh);
                    mma16816(d[ntj], xah[kt], bl);
                    mma16816(d[ntj], xal[kt], bh);
                }
            }
            const int ten = ch >> 1;
            const float bmult = (ten == 0 || ten == 3) ? QSCALE : 1.0f;
            const float* bsrc = (ten < 3) ? (bqkv + ten * 128) : (bqkv2 + (ten - 3) * 128);
            const int r0 = mg * 16 + (lid >> 2);
            const int ibase = (ten == 0) ? 65536 : (ten == 1) ? 98304
                            : (ten == 2) ? 196608 : (ten == 3) ? 131072 : 163840;
            char* img = smc + ibase;
            #pragma unroll
            for (int nt = 0; nt < 2; nt++) {
                int tc = (ch & 1) * 64 + wg * 16 + nt * 8 + 2 * (lid & 3);
                float b0 = __ldg(bsrc + tc) * bmult, b1 = __ldg(bsrc + tc + 1) * bmult;
                float v0 = d[nt][0] + b0, v1 = d[nt][1] + b1;
                float v2 = d[nt][2] + b0, v3 = d[nt][3] + b1;
                int c2 = tc * 2;
                __nv_bfloat16 h0 = __float2bfloat16(v0), h1 = __float2bfloat16(v1);
                __nv_bfloat16 h2 = __float2bfloat16(v2), h3 = __float2bfloat16(v3);
                u32 hp01 = (u32)bfbits(h0) | ((u32)bfbits(h1) << 16);
                u32 hp23 = (u32)bfbits(h2) | ((u32)bfbits(h3) << 16);
                __nv_bfloat16 l0 = __float2bfloat16(v0 - __bfloat162float(h0));
                __nv_bfloat16 l1 = __float2bfloat16(v1 - __bfloat162float(h1));
                __nv_bfloat16 l2 = __float2bfloat16(v2 - __bfloat162float(h2));
                __nv_bfloat16 l3 = __float2bfloat16(v3 - __bfloat162float(h3));
                u32 lp01 = (u32)bfbits(l0) | ((u32)bfbits(l1) << 16);
                u32 lp23 = (u32)bfbits(l2) | ((u32)bfbits(l3) << 16);
                int s0 = BSW(r0, c2), s1 = BSW(r0 + 8, c2);
                *(u32*)(img + s0)         = hp01;
                *(u32*)(img + 16384 + s0) = lp01;
                *(u32*)(img + s1)         = hp23;
                *(u32*)(img + 16384 + s1) = lp23;
            }
        }
    }
    __syncthreads();

    // ---- differential attention: att in region A, 2 syncs/head, FULLY UNROLLED
    //      head loop (static o[h] indexing -> no local-memory spills) ----
    const float lam = g_lam;
    const float* pbm = g_pbm + (size_t)(b % NWIN) * (NH * NTOK * NTOK);
    const int r0 = mg * 16 + (lid >> 2);
    const int n = t >> 3, qd = t & 7;
    float* att = sm;                          // region A, stride 68
    float o[4][4];
    #pragma unroll
    for (int h = 0; h < 4; h++)
        #pragma unroll
        for (int i = 0; i < 4; i++) o[h][i] = 0.f;

    #pragma unroll
    for (int h = 0; h < 4; h++) {
        // -- prefetch pbm (off the MMA->store critical path) --
        float2 pb0[2], pb1[2];
        #pragma unroll
        for (int nt = 0; nt < 2; nt++) {
            int col = wg * 16 + nt * 8 + 2 * (lid & 3);
            pb0[nt] = __ldg((const float2*)(pbm + h * 4096 + r0 * 64 + col));
            pb1[nt] = __ldg((const float2*)(pbm + h * 4096 + (r0 + 8) * 64 + col));
        }

        // -- logits: d1 = q.k^T, d2 = q2.k2^T (3-term hi/lo each) --
        {
            float d1[2][4], d2[2][4];
            #pragma unroll
            for (int nt = 0; nt < 2; nt++)
                #pragma unroll
                for (int i = 0; i < 4; i++) { d1[nt][i] = 0.f; d2[nt][i] = 0.f; }
            const int ar = mg * 16 + (lid & 15);
            const int abyte = h * 64 + (lid & 16);
            const int bc = wg * 16 + (lid & 7);
            const int bbyte = h * 64 + ((lid & 8) << 1);
            #pragma unroll
            for (int ks = 0; ks < 2; ks++) {
                u32 aoff = BSW(ar, abyte + ks * 32);
                u32 qh[4], ql[4], q2h[4], q2l[4];
                ldsm4(qh,  smb +  65536 + aoff);
                ldsm4(ql,  smb +  81920 + aoff);
                ldsm4(q2h, smb + 131072 + aoff);
                ldsm4(q2l, smb + 147456 + aoff);
                #pragma unroll
                for (int nt = 0; nt < 2; nt++) {
                    u32 boff = BSW(bc + nt * 8, bbyte + ks * 32);
                    u32 kh[2], kl[2], k2h[2], k2l[2];
                    ldsm2(kh,  smb +  98304 + boff);
                    ldsm2(kl,  smb + 114688 + boff);
                    ldsm2(k2h, smb + 163840 + boff);
                    ldsm2(k2l, smb + 180224 + boff);
                    mma16816(d1[nt], qh, kh);
                    mma16816(d1[nt], qh, kl);
                    mma16816(d1[nt], ql, kh);
                    mma16816(d2[nt], q2h, k2h);
                    mma16816(d2[nt], q2h, k2l);
                    mma16816(d2[nt], q2l, k2h);
                }
            }
            #pragma unroll
            for (int nt = 0; nt < 2; nt++) {
                int col = wg * 16 + nt * 8 + 2 * (lid & 3);
                *(float2*)(att + r0 * 68 + col) =
                    make_float2(fmaf(-lam, d2[nt][0], d1[nt][0]) + pb0[nt].x,
                                fmaf(-lam, d2[nt][1], d1[nt][1]) + pb0[nt].y);
                *(float2*)(att + (r0 + 8) * 68 + col) =
                    make_float2(fmaf(-lam, d2[nt][2], d1[nt][2]) + pb1[nt].x,
                                fmaf(-lam, d2[nt][3], d1[nt][3]) + pb1[nt].y);
            }
        }
        __syncthreads();   // att ready; also orders prior-head AV P-reads before new P stores

        // -- softmax: lane owns 8 contiguous cols [qd*8, qd*8+8) of row n;
        //    P images (region B) do not alias att (region A) --
        {
            float p[8];
            float4 L0 = *(const float4*)(att + n * 68 + qd * 8);
            float4 L1 = *(const float4*)(att + n * 68 + qd * 8 + 4);
            p[0] = L0.x; p[1] = L0.y; p[2] = L0.z; p[3] = L0.w;
            p[4] = L1.x; p[5] = L1.y; p[6] = L1.z; p[7] = L1.w;
            float M = p[0];
            #pragma unroll
            for (int j = 1; j < 8; j++) M = fmaxf(M, p[j]);
            M = fmaxf(M, __shfl_xor_sync(0xffffffffu, M, 1));
            M = fmaxf(M, __shfl_xor_sync(0xffffffffu, M, 2));
            M = fmaxf(M, __shfl_xor_sync(0xffffffffu, M, 4));
            float S = 0.f;
            #pragma unroll
            for (int j = 0; j < 8; j++) { p[j] = __expf(p[j] - M); S += p[j]; }
            S += __shfl_xor_sync(0xffffffffu, S, 1);
            S += __shfl_xor_sync(0xffffffffu, S, 2);
            S += __shfl_xor_sync(0xffffffffu, S, 4);
            float inv = 1.0f / S;
            u32 hp[4], lp[4];
            #pragma unroll
            for (int j = 0; j < 4; j++) {
                float v0 = p[2 * j] * inv, v1 = p[2 * j + 1] * inv;
                __nv_bfloat16 h0 = __float2bfloat16(v0), h1 = __float2bfloat16(v1);
                hp[j] = (u32)bfbits(h0) | ((u32)bfbits(h1) << 16);
                __nv_bfloat16 l0 = __float2bfloat16(v0 - __bfloat162float(h0));
                __nv_bfloat16 l1 = __float2bfloat16(v1 - __bfloat162float(h1));
                lp[j] = (u32)bfbits(l0) | ((u32)bfbits(l1) << 16);
            }
            int sw = BSW128(n, qd * 16);
            *(uint4*)(smc + 32768 + sw) = make_uint4(hp[0], hp[1], hp[2], hp[3]);
            *(uint4*)(smc + 40960 + sw) = make_uint4(lp[0], lp[1], lp[2], lp[3]);
        }
        __syncthreads();   // P ready

        // -- o[h] += P @ V via mma.sync (static h -> register accumulators) --
        {
            const int ar = mg * 16 + (lid & 15);
            const int ak = (lid & 16);
            #pragma unroll
            for (int ks = 0; ks < 4; ks++) {
                u32 ph4[4], pl4[4];
                u32 paddr = smb + 32768 + BSW128(ar, ks * 32 + ak);
                ldsm4(ph4, paddr);
                ldsm4(pl4, paddr + 8192);
                u32 vh[2], vl[2];
                u32 vaddr = smb + 196608 + BSW(ks * 16 + (lid & 15), h * 64 + wg * 16);
                ldsm2t(vh, vaddr);
                ldsm2t(vl, vaddr + 16384);
                mma16816(o[h], ph4, vh);
                mma16816(o[h], ph4, vl);
                mma16816(o[h], pl4, vh);
            }
        }
    }
    __syncthreads();   // att dead; all AV complete -> region A becomes os tile

    // ---- store o-fragments into os tile (region A) ----
    {
        float* ost = sm;
        #pragma unroll
        for (int h = 0; h < 4; h++) {
            int c = h * 32 + wg * 8 + 2 * (lid & 3);
            int g = c >> 2, sub = c & 3;
            *(float2*)(ost + SWZ(r0, g) * 4 + sub)     = make_float2(o[h][0], o[h][1]);
            *(float2*)(ost + SWZ(r0 + 8, g) * 4 + sub) = make_float2(o[h][2], o[h][3]);
        }
    }
    __syncthreads();

    // ---- RMSNorm fused with bf16 image conversion (os images -> k region) ----
    {
        const float* ost = (const float*)sm;
        #pragma unroll
        for (int h = 0; h < 4; h++) {
            int g = h * 8 + qd;
            float4 v4 = ((const float4*)ost)[SWZ(n, g)];
            float s = v4.x * v4.x + v4.y * v4.y + v4.z * v4.z + v4.w * v4.w;
            s += __shfl_xor_sync(0xffffffffu, s, 1);
            s += __shfl_xor_sync(0xffffffffu, s, 2);
            s += __shfl_xor_sync(0xffffffffu, s, 4);
            float rs = rsqrtf(s * (1.0f / 32.0f) + 1e-9f);
            v4.x *= rs; v4.y *= rs; v4.z *= rs; v4.w *= rs;
            __nv_bfloat16 h0 = __float2bfloat16(v4.x), h1 = __float2bfloat16(v4.y);
            __nv_bfloat16 h2 = __float2bfloat16(v4.z), h3 = __float2bfloat16(v4.w);
            __nv_bfloat16 l0 = __float2bfloat16(v4.x - __bfloat162float(h0));
            __nv_bfloat16 l1 = __float2bfloat16(v4.y - __bfloat162float(h1));
            __nv_bfloat16 l2 = __float2bfloat16(v4.z - __bfloat162float(h2));
            __nv_bfloat16 l3 = __float2bfloat16(v4.w - __bfloat162float(h3));
            u64 hp = (u64)bfbits(h0) | ((u64)bfbits(h1) << 16) | ((u64)bfbits(h2) << 32) | ((u64)bfbits(h3) << 48);
            u64 lp = (u64)bfbits(l0) | ((u64)bfbits(l1) << 16) | ((u64)bfbits(l2) << 32) | ((u64)bfbits(l3) << 48);
            int sw = BSW(n, g * 8);
            *(u64*)(smc +  98304 + sw) = hp;
            *(u64*)(smc + 114688 + sw) = lp;
        }
    }
    __syncthreads();

    // ---- proj: A-fragments from os images; B-fragments from gmem ----
    {
        u32 oah[8][4], oal[8][4];
        {
            const int ar = mg * 16 + (lid & 15);
            const int ak = (lid & 16);
            #pragma unroll
            for (int kt = 0; kt < 8; kt++) {
                int off = BSW(ar, kt * 32 + ak);
                ldsm4(oah[kt], smb +  98304 + off);
                ldsm4(oal[kt], smb + 114688 + off);
            }
        }
        float* og = out + (size_t)b * (NTOK * DIM);
        #pragma unroll 1
        for (int pc = 0; pc < 2; pc++) {
            const u64* wf = g_wf + (10 + pc) * 4096 + wg * 64 + lid;
            float d[2][4];
            #pragma unroll
            for (int nt = 0; nt < 2; nt++)
                #pragma unroll
                for (int i = 0; i < 4; i++) d[nt][i] = 0.f;
            #pragma unroll
            for (int kt = 0; kt < 8; kt++) {
                #pragma unroll
                for (int ntj = 0; ntj < 2; ntj++) {
                    u64 bhv = __ldg(wf + kt * 256 + ntj * 32);
                    u64 blv = __ldg(wf + 2048 + kt * 256 + ntj * 32);
                    u32 bh[2] = {(u32)bhv, (u32)(bhv >> 32)};
                    u32 bl[2] = {(u32)blv, (u32)(blv >> 32)};
                    mma16816(d[ntj], oah[kt], bh);
                    mma16816(d[ntj], oah[kt], bl);
                    mma16816(d[ntj], oal[kt], bh);
                }
            }
            #pragma unroll
            for (int nt = 0; nt < 2; nt++) {
                int cg = pc * 64 + wg * 16 + nt * 8 + 2 * (lid & 3);
                float b0 = __ldg(bproj + cg), b1 = __ldg(bproj + cg + 1);
                *(float2*)(og + r0 * 128 + cg)       = make_float2(d[nt][0] + b0, d[nt][1] + b1);
                *(float2*)(og + (r0 + 8) * 128 + cg) = make_float2(d[nt][2] + b0, d[nt][3] + b1);
            }
        }
    }
}

// ---------------------------------------------------------------------------
extern "C" void kernel_launch(void* const* d_in, const int* in_sizes, int n_in,
                              void* d_out, int out_size)
{
    const float* x      = (const float*)d_in[0];
    const float* mask   = (const float*)d_in[1];
    const float* Wqkv   = (const float*)d_in[2];
    const float* bqkv   = (const float*)d_in[3];
    const float* Wqkv2  = (const float*)d_in[4];
    const float* bqkv2  = (const float*)d_in[5];
    const float* Wp1    = (const float*)d_in[6];
    const float* bp1    = (const float*)d_in[7];
    const float* Wp2    = (const float*)d_in[8];
    const float* bp2    = (const float*)d_in[9];
    const float* lq1    = (const float*)d_in[10];
    const float* lk1    = (const float*)d_in[11];
    const float* lq2    = (const float*)d_in[12];
    const float* lk2    = (const float*)d_in[13];
    const float* subln  = (const float*)d_in[14];
    const float* Wproj  = (const float*)d_in[15];
    const float* bproj  = (const float*)d_in[16];
    float* out = (float*)d_out;

    const int SMEM = 229376;
    cudaFuncSetAttribute(wattn_kernel, cudaFuncAttributeMaxDynamicSharedMemorySize, SMEM);

    prep1_kernel<<<16, 256>>>(Wp1, bp1, Wp2, bp2, lq1, lk1, lq2, lk2);
    prep2_kernel<<<(NWIN * NH * NTOK * NTOK) / 256, 256>>>(mask);
    prepw_kernel<<<192, 256>>>(Wqkv, Wqkv2, Wproj, subln);
    wattn_kernel<<<B_TOT, NTHR, SMEM>>>(x, bqkv, bqkv2, bproj, out);
}